// round 1
// baseline (speedup 1.0000x reference)
#include <cuda_runtime.h>

// Problem constants (fixed by the dataset)
#define NN 50000
#define EE 800000
#define DD 128
#define GG 64
#define CC 8

// ---------------- scratch (static device globals; no allocation) ----------------
__device__ float g_xw0[NN * DD];
__device__ float g_xw1[NN * DD];
__device__ float g_agg[NN * DD];    // layer-0 output
__device__ float g_out2[NN * DD];   // layer-1 output
__device__ float g_invd0[NN];
__device__ float g_invd1[NN];
__device__ float g_pooled[GG * DD];
__device__ int   g_counts[GG];
__device__ int   g_offsets[GG + 1];

// ---------------- degree / normalization ----------------
__global__ void init_invd() {
    int i = blockIdx.x * blockDim.x + threadIdx.x;
    if (i < NN) { g_invd0[i] = 1.0f; g_invd1[i] = 1.0f; }
}

__global__ void deg_accum(const int* __restrict__ dst, float* __restrict__ deg) {
    int e = blockIdx.x * blockDim.x + threadIdx.x;
    if (e < EE) atomicAdd(&deg[dst[e]], 1.0f);
}

__global__ void finalize_invd() {
    int i = blockIdx.x * blockDim.x + threadIdx.x;
    if (i < NN) {
        g_invd0[i] = rsqrtf(g_invd0[i]);
        g_invd1[i] = rsqrtf(g_invd1[i]);
    }
}

// ---------------- GEMM: C[N,128] = act(A)[N,128] @ W[128,128] ----------------
// BM=64, BN=128, BK=8, thread tile 8x4, 256 threads/block.
template <bool RELU>
__global__ void gemm128(const float* __restrict__ A, const float* __restrict__ W,
                        float* __restrict__ C) {
    __shared__ float As[8][64];
    __shared__ float Bs[8][128];
    const int tid  = threadIdx.x;
    const int trow = tid >> 5;    // 0..7
    const int tcol = tid & 31;    // 0..31
    const int rowBase = blockIdx.x * 64;

    float acc[8][4] = {};

    for (int k0 = 0; k0 < DD; k0 += 8) {
        // load A tile (64 rows x 8 k), transposed into As[k][row]
        #pragma unroll
        for (int i = 0; i < 2; ++i) {
            int e = tid + i * 256;
            int r = e >> 3, k = e & 7;
            int gr = rowBase + r;
            float v = (gr < NN) ? A[gr * DD + k0 + k] : 0.0f;
            if (RELU) v = fmaxf(v, 0.0f);
            As[k][r] = v;
        }
        // load W tile (8 k x 128 cols), coalesced
        #pragma unroll
        for (int i = 0; i < 4; ++i) {
            int e = tid + i * 256;
            int k = e >> 7, c = e & 127;
            Bs[k][c] = W[(k0 + k) * DD + c];
        }
        __syncthreads();

        #pragma unroll
        for (int k = 0; k < 8; ++k) {
            float a[8], bb[4];
            #pragma unroll
            for (int i = 0; i < 8; ++i) a[i] = As[k][trow * 8 + i];
            #pragma unroll
            for (int j = 0; j < 4; ++j) bb[j] = Bs[k][tcol * 4 + j];
            #pragma unroll
            for (int i = 0; i < 8; ++i)
                #pragma unroll
                for (int j = 0; j < 4; ++j)
                    acc[i][j] = fmaf(a[i], bb[j], acc[i][j]);
        }
        __syncthreads();
    }

    #pragma unroll
    for (int i = 0; i < 8; ++i) {
        int gr = rowBase + trow * 8 + i;
        if (gr < NN) {
            float4 v = make_float4(acc[i][0], acc[i][1], acc[i][2], acc[i][3]);
            *reinterpret_cast<float4*>(&C[gr * DD + tcol * 4]) = v;
        }
    }
}

// ---------------- per-layer init: self-loop terms + biases (overwrites agg) ----------------
__global__ void agg_init(const float4* __restrict__ xw0, const float4* __restrict__ xw1,
                         const float* __restrict__ b_l, float4* __restrict__ agg) {
    int idx = blockIdx.x * blockDim.x + threadIdx.x;   // over NN*32 float4s
    if (idx >= NN * 32) return;
    int i = idx >> 5, q = idx & 31;
    float s0 = g_invd0[i]; s0 *= s0;
    float s1 = g_invd1[i]; s1 *= s1;
    float4 a = xw0[idx];
    float4 c = xw1[idx];
    int d0 = q << 2;
    float4 r;
    r.x = fmaf(a.x, s0, c.x * s1) + b_l[d0 + 0] + b_l[DD + d0 + 0];
    r.y = fmaf(a.y, s0, c.y * s1) + b_l[d0 + 1] + b_l[DD + d0 + 1];
    r.z = fmaf(a.z, s0, c.z * s1) + b_l[d0 + 2] + b_l[DD + d0 + 2];
    r.w = fmaf(a.w, s0, c.w * s1) + b_l[d0 + 3] + b_l[DD + d0 + 3];
    agg[idx] = r;
}

// ---------------- edge scatter: warp per edge, float4 vector atomics ----------------
__global__ void scatter_edges(const float* __restrict__ xw,
                              const int* __restrict__ src, const int* __restrict__ dst,
                              const float* __restrict__ invd, float* __restrict__ agg) {
    int t = blockIdx.x * blockDim.x + threadIdx.x;
    int e = t >> 5;
    int lane = t & 31;
    if (e >= EE) return;
    int s = src[e];
    int d = dst[e];
    float w = invd[s] * invd[d];
    float4 v = *reinterpret_cast<const float4*>(xw + (size_t)s * DD + lane * 4);
    v.x *= w; v.y *= w; v.z *= w; v.w *= w;
    float* p = agg + (size_t)d * DD + lane * 4;
    asm volatile("red.global.add.v4.f32 [%0], {%1, %2, %3, %4};"
                 :: "l"(p), "f"(v.x), "f"(v.y), "f"(v.z), "f"(v.w) : "memory");
}

// ---------------- pooling ----------------
__global__ void zero_pool() {
    int i = blockIdx.x * blockDim.x + threadIdx.x;
    if (i < GG) g_counts[i] = 0;
    if (i < GG * DD) g_pooled[i] = 0.0f;
}

__global__ void count_batch(const int* __restrict__ batch) {
    int i = blockIdx.x * blockDim.x + threadIdx.x;
    if (i < NN) atomicAdd(&g_counts[batch[i]], 1);
}

__global__ void scan_counts() {
    if (threadIdx.x == 0) {
        int acc = 0;
        for (int g = 0; g < GG; ++g) { g_offsets[g] = acc; acc += g_counts[g]; }
        g_offsets[GG] = acc;
    }
}

// batch is sorted -> nodes of graph g are contiguous [offsets[g], offsets[g+1])
__global__ void pool_partial(const float* __restrict__ h) {
    int g = blockIdx.x;
    int chunk = blockIdx.y;           // gridDim.y chunks per graph
    int d = threadIdx.x;              // 128 dims
    int start = g_offsets[g], end = g_offsets[g + 1];
    int n = end - start;
    int per = (n + (int)gridDim.y - 1) / (int)gridDim.y;
    int s = start + chunk * per;
    int e = min(end, s + per);
    float acc = 0.0f;
    for (int i = s; i < e; ++i) acc += h[(size_t)i * DD + d];
    atomicAdd(&g_pooled[g * DD + d], acc);
}

__global__ void final_linear(const float* __restrict__ lin_w,
                             const float* __restrict__ lin_b,
                             float* __restrict__ out) {
    int t = threadIdx.x;              // GG*CC = 512
    int g = t >> 3, c = t & 7;
    float cnt = (float)max(g_counts[g], 1);
    float acc = 0.0f;
    #pragma unroll 16
    for (int d = 0; d < DD; ++d) acc += g_pooled[g * DD + d] * lin_w[d * CC + c];
    out[g * CC + c] = acc / cnt + lin_b[c];
}

// ---------------- launch ----------------
extern "C" void kernel_launch(void* const* d_in, const int* in_sizes, int n_in,
                              void* d_out, int out_size) {
    const float* x     = (const float*)d_in[0];
    const float* W     = (const float*)d_in[1];   // [L,R,D,D]
    const float* b     = (const float*)d_in[2];   // [L,R,D]
    const float* lin_w = (const float*)d_in[3];   // [D,C]
    const float* lin_b = (const float*)d_in[4];   // [C]
    const int*   ei    = (const int*)d_in[5];     // [R,2,E]
    const int*   batch = (const int*)d_in[6];     // [N]
    float* out = (float*)d_out;

    float *xw0, *xw1, *agg, *out2, *invd0, *invd1;
    cudaGetSymbolAddress((void**)&xw0,   g_xw0);
    cudaGetSymbolAddress((void**)&xw1,   g_xw1);
    cudaGetSymbolAddress((void**)&agg,   g_agg);
    cudaGetSymbolAddress((void**)&out2,  g_out2);
    cudaGetSymbolAddress((void**)&invd0, g_invd0);
    cudaGetSymbolAddress((void**)&invd1, g_invd1);

    const int* src0 = ei + 0 * EE;
    const int* dst0 = ei + 1 * EE;
    const int* src1 = ei + 2 * EE;
    const int* dst1 = ei + 3 * EE;

    const int TB = 256;
    int nodeBlocks = (NN + TB - 1) / TB;
    int edgeBlocks = (EE + TB - 1) / TB;
    int gemmBlocks = (NN + 63) / 64;
    int vecBlocks  = (NN * 32 + TB - 1) / TB;
    int scatBlocks = ((EE * 32) + TB - 1) / TB;

    // normalization (recomputed every call; deterministic)
    init_invd<<<nodeBlocks, TB>>>();
    deg_accum<<<edgeBlocks, TB>>>(dst0, invd0);
    deg_accum<<<edgeBlocks, TB>>>(dst1, invd1);
    finalize_invd<<<nodeBlocks, TB>>>();

    // ---- layer 0 (input = x, no activation on load) ----
    gemm128<false><<<gemmBlocks, TB>>>(x, W + 0 * DD * DD, xw0);
    gemm128<false><<<gemmBlocks, TB>>>(x, W + 1 * DD * DD, xw1);
    agg_init<<<vecBlocks, TB>>>((const float4*)xw0, (const float4*)xw1, b + 0, (float4*)agg);
    scatter_edges<<<scatBlocks, TB>>>(xw0, src0, dst0, invd0, agg);
    scatter_edges<<<scatBlocks, TB>>>(xw1, src1, dst1, invd1, agg);

    // ---- layer 1 (input = relu(agg), relu fused into GEMM A-load) ----
    gemm128<true><<<gemmBlocks, TB>>>(agg, W + 2 * DD * DD, xw0);
    gemm128<true><<<gemmBlocks, TB>>>(agg, W + 3 * DD * DD, xw1);
    agg_init<<<vecBlocks, TB>>>((const float4*)xw0, (const float4*)xw1, b + 2 * DD, (float4*)out2);
    scatter_edges<<<scatBlocks, TB>>>(xw0, src0, dst0, invd0, out2);
    scatter_edges<<<scatBlocks, TB>>>(xw1, src1, dst1, invd1, out2);

    // ---- pooling + classifier ----
    zero_pool<<<(GG * DD + TB - 1) / TB, TB>>>();
    count_batch<<<nodeBlocks, TB>>>(batch);
    scan_counts<<<1, 32>>>();
    dim3 pg(GG, 8);
    pool_partial<<<pg, DD>>>(out2);
    final_linear<<<1, GG * CC>>>(lin_w, lin_b, out);
}

// round 2
// speedup vs baseline: 1.2591x; 1.2591x over previous
#include <cuda_runtime.h>

#define NN 50000
#define EE 800000
#define DD 128
#define GG 64
#define CC 8

// ---------------- static scratch ----------------
__device__ float g_xw[NN * 256];        // [N, 256]: cols 0-127 rel0, 128-255 rel1
__device__ float g_agg[NN * DD];        // layer output (reused both layers)
__device__ float g_invd0[NN];
__device__ float g_invd1[NN];
__device__ int   g_deg0[NN];
__device__ int   g_deg1[NN];
__device__ int   g_ptr0[NN + 1];
__device__ int   g_ptr1[NN + 1];
__device__ int   g_cur0[NN];
__device__ int   g_cur1[NN];
__device__ int2  g_ce0[EE];             // packed {src, weight bits}
__device__ int2  g_ce1[EE];
__device__ float g_pooled[GG * DD];
__device__ int   g_counts[GG];
__device__ int   g_offsets[GG + 1];

// ---------------- setup kernels ----------------
__global__ void zero_all() {
    int i = blockIdx.x * blockDim.x + threadIdx.x;
    if (i < NN) { g_deg0[i] = 0; g_deg1[i] = 0; }
    if (i < GG) g_counts[i] = 0;
    if (i < GG * DD) g_pooled[i] = 0.0f;
}

__global__ void hist(const int* __restrict__ dst, int* __restrict__ deg) {
    int e = blockIdx.x * blockDim.x + threadIdx.x;
    if (e < EE) atomicAdd(&deg[dst[e]], 1);
}

__global__ void make_invd() {
    int i = blockIdx.x * blockDim.x + threadIdx.x;
    if (i < NN) {
        g_invd0[i] = rsqrtf((float)(g_deg0[i] + 1));
        g_invd1[i] = rsqrtf((float)(g_deg1[i] + 1));
    }
}

// exclusive scan over NN counts -> ptr (NN+1) and cursor copy; one block of 1024
__global__ void exscan(const int* __restrict__ cnt, int* __restrict__ ptr,
                       int* __restrict__ cursor) {
    __shared__ int part[1024];
    int tid = threadIdx.x;
    const int PER = (NN + 1023) / 1024;
    int start = tid * PER;
    int end = min(NN, start + PER);
    int s = 0;
    for (int i = start; i < end; ++i) s += cnt[i];
    part[tid] = s;
    __syncthreads();
    for (int off = 1; off < 1024; off <<= 1) {
        int v = (tid >= off) ? part[tid - off] : 0;
        __syncthreads();
        part[tid] += v;
        __syncthreads();
    }
    int base = (tid == 0) ? 0 : part[tid - 1];
    for (int i = start; i < end; ++i) {
        ptr[i] = base; cursor[i] = base;
        base += cnt[i];
    }
    if (tid == 1023) ptr[NN] = part[1023];
}

__global__ void csr_fill(const int* __restrict__ src, const int* __restrict__ dst,
                         const float* __restrict__ invd, int* __restrict__ cursor,
                         int2* __restrict__ ce) {
    int e = blockIdx.x * blockDim.x + threadIdx.x;
    if (e >= EE) return;
    int s = src[e], d = dst[e];
    int slot = atomicAdd(&cursor[d], 1);
    int2 p; p.x = s; p.y = __float_as_int(invd[s] * invd[d]);
    ce[slot] = p;
}

// ---------------- GEMM: out[N,256] (rel = blockIdx.y) = act(A)[N,128] @ W[rel] ----------------
// BM=128, BN=128, BK=8, 8x8 microtile, 256 threads.
template <bool RELU>
__global__ void __launch_bounds__(256, 2)
gemm_dual(const float* __restrict__ A, const float* __restrict__ Wl,
          float* __restrict__ out) {
    const int rel = blockIdx.y;
    const float* Wr = Wl + rel * DD * DD;
    const int rowBase = blockIdx.x * 128;
    __shared__ float As[8][132];
    __shared__ float Bs[8][132];
    const int tid = threadIdx.x;
    const int tx = tid & 15, ty = tid >> 4;

    float acc[8][8] = {};

    const int lr = tid >> 1;            // 0..127
    const int lk = (tid & 1) * 4;       // 0 or 4
    const int bk = tid >> 5;            // 0..7
    const int bc = (tid & 31) * 4;      // 0..124

    for (int k0 = 0; k0 < DD; k0 += 8) {
        float4 av = make_float4(0.f, 0.f, 0.f, 0.f);
        int gr = rowBase + lr;
        if (gr < NN) av = *reinterpret_cast<const float4*>(A + (size_t)gr * DD + k0 + lk);
        if (RELU) {
            av.x = fmaxf(av.x, 0.f); av.y = fmaxf(av.y, 0.f);
            av.z = fmaxf(av.z, 0.f); av.w = fmaxf(av.w, 0.f);
        }
        As[lk + 0][lr] = av.x; As[lk + 1][lr] = av.y;
        As[lk + 2][lr] = av.z; As[lk + 3][lr] = av.w;

        float4 bv = *reinterpret_cast<const float4*>(Wr + (k0 + bk) * DD + bc);
        *reinterpret_cast<float4*>(&Bs[bk][bc]) = bv;
        __syncthreads();

        #pragma unroll
        for (int k = 0; k < 8; ++k) {
            float a[8], bb[8];
            *reinterpret_cast<float4*>(a)      = *reinterpret_cast<const float4*>(&As[k][ty * 4]);
            *reinterpret_cast<float4*>(a + 4)  = *reinterpret_cast<const float4*>(&As[k][64 + ty * 4]);
            *reinterpret_cast<float4*>(bb)     = *reinterpret_cast<const float4*>(&Bs[k][tx * 4]);
            *reinterpret_cast<float4*>(bb + 4) = *reinterpret_cast<const float4*>(&Bs[k][64 + tx * 4]);
            #pragma unroll
            for (int i = 0; i < 8; ++i)
                #pragma unroll
                for (int j = 0; j < 8; ++j)
                    acc[i][j] = fmaf(a[i], bb[j], acc[i][j]);
        }
        __syncthreads();
    }

    // store: rows {ty*4+i, 64+ty*4+i}, cols rel*128 + {tx*4.., 64+tx*4..}
    #pragma unroll
    for (int half = 0; half < 2; ++half) {
        #pragma unroll
        for (int i = 0; i < 4; ++i) {
            int r = rowBase + half * 64 + ty * 4 + i;
            if (r < NN) {
                int ai = half * 4 + i;
                float* op = out + (size_t)r * 256 + rel * 128;
                *reinterpret_cast<float4*>(op + tx * 4) =
                    make_float4(acc[ai][0], acc[ai][1], acc[ai][2], acc[ai][3]);
                *reinterpret_cast<float4*>(op + 64 + tx * 4) =
                    make_float4(acc[ai][4], acc[ai][5], acc[ai][6], acc[ai][7]);
            }
        }
    }
}

// ---------------- fused aggregation: self-loop + bias + CSR gather over both relations ----------------
__global__ void gather_both(const float* __restrict__ xw,
                            const float* __restrict__ b_l,
                            float* __restrict__ agg) {
    int t = blockIdx.x * blockDim.x + threadIdx.x;
    int i = t >> 5;
    int lane = t & 31;
    if (i >= NN) return;
    int c4 = lane * 4;

    float s0 = g_invd0[i]; s0 *= s0;
    float s1 = g_invd1[i]; s1 *= s1;
    const float4* row = reinterpret_cast<const float4*>(xw + (size_t)i * 256);
    float4 v0 = row[lane];
    float4 v1 = row[32 + lane];
    float4 acc;
    acc.x = fmaf(v0.x, s0, v1.x * s1) + b_l[c4 + 0] + b_l[DD + c4 + 0];
    acc.y = fmaf(v0.y, s0, v1.y * s1) + b_l[c4 + 1] + b_l[DD + c4 + 1];
    acc.z = fmaf(v0.z, s0, v1.z * s1) + b_l[c4 + 2] + b_l[DD + c4 + 2];
    acc.w = fmaf(v0.w, s0, v1.w * s1) + b_l[c4 + 3] + b_l[DD + c4 + 3];

    // relation 0
    {
        int b0 = g_ptr0[i], e0 = g_ptr0[i + 1];
        int tt = b0;
        for (; tt + 1 < e0; tt += 2) {
            int2 pA = g_ce0[tt], pB = g_ce0[tt + 1];
            float wA = __int_as_float(pA.y), wB = __int_as_float(pB.y);
            float4 vA = *reinterpret_cast<const float4*>(xw + (size_t)pA.x * 256 + c4);
            float4 vB = *reinterpret_cast<const float4*>(xw + (size_t)pB.x * 256 + c4);
            acc.x = fmaf(wA, vA.x, fmaf(wB, vB.x, acc.x));
            acc.y = fmaf(wA, vA.y, fmaf(wB, vB.y, acc.y));
            acc.z = fmaf(wA, vA.z, fmaf(wB, vB.z, acc.z));
            acc.w = fmaf(wA, vA.w, fmaf(wB, vB.w, acc.w));
        }
        if (tt < e0) {
            int2 p = g_ce0[tt];
            float w = __int_as_float(p.y);
            float4 v = *reinterpret_cast<const float4*>(xw + (size_t)p.x * 256 + c4);
            acc.x = fmaf(w, v.x, acc.x); acc.y = fmaf(w, v.y, acc.y);
            acc.z = fmaf(w, v.z, acc.z); acc.w = fmaf(w, v.w, acc.w);
        }
    }
    // relation 1 (cols 128..255)
    {
        int b1 = g_ptr1[i], e1 = g_ptr1[i + 1];
        int tt = b1;
        for (; tt + 1 < e1; tt += 2) {
            int2 pA = g_ce1[tt], pB = g_ce1[tt + 1];
            float wA = __int_as_float(pA.y), wB = __int_as_float(pB.y);
            float4 vA = *reinterpret_cast<const float4*>(xw + (size_t)pA.x * 256 + 128 + c4);
            float4 vB = *reinterpret_cast<const float4*>(xw + (size_t)pB.x * 256 + 128 + c4);
            acc.x = fmaf(wA, vA.x, fmaf(wB, vB.x, acc.x));
            acc.y = fmaf(wA, vA.y, fmaf(wB, vB.y, acc.y));
            acc.z = fmaf(wA, vA.z, fmaf(wB, vB.z, acc.z));
            acc.w = fmaf(wA, vA.w, fmaf(wB, vB.w, acc.w));
        }
        if (tt < e1) {
            int2 p = g_ce1[tt];
            float w = __int_as_float(p.y);
            float4 v = *reinterpret_cast<const float4*>(xw + (size_t)p.x * 256 + 128 + c4);
            acc.x = fmaf(w, v.x, acc.x); acc.y = fmaf(w, v.y, acc.y);
            acc.z = fmaf(w, v.z, acc.z); acc.w = fmaf(w, v.w, acc.w);
        }
    }
    *reinterpret_cast<float4*>(agg + (size_t)i * DD + c4) = acc;
}

// ---------------- pooling + classifier ----------------
__global__ void count_batch(const int* __restrict__ batch) {
    int i = blockIdx.x * blockDim.x + threadIdx.x;
    if (i < NN) atomicAdd(&g_counts[batch[i]], 1);
}

__global__ void scan64() {
    if (threadIdx.x == 0) {
        int acc = 0;
        for (int g = 0; g < GG; ++g) { g_offsets[g] = acc; acc += g_counts[g]; }
        g_offsets[GG] = acc;
    }
}

__global__ void pool_partial(const float* __restrict__ h) {
    int g = blockIdx.x;
    int chunk = blockIdx.y;
    int d = threadIdx.x;
    int start = g_offsets[g], end = g_offsets[g + 1];
    int n = end - start;
    int per = (n + (int)gridDim.y - 1) / (int)gridDim.y;
    int s = start + chunk * per;
    int e = min(end, s + per);
    float acc = 0.0f;
    for (int i = s; i < e; ++i) acc += h[(size_t)i * DD + d];
    if (acc != 0.0f || s < e) atomicAdd(&g_pooled[g * DD + d], acc);
}

__global__ void final_linear(const float* __restrict__ lin_w,
                             const float* __restrict__ lin_b,
                             float* __restrict__ out) {
    int t = threadIdx.x;            // 512 = GG*CC
    int g = t >> 3, c = t & 7;
    float cnt = (float)max(g_counts[g], 1);
    float acc = 0.0f;
    #pragma unroll 16
    for (int d = 0; d < DD; ++d) acc += g_pooled[g * DD + d] * lin_w[d * CC + c];
    out[g * CC + c] = acc / cnt + lin_b[c];
}

// ---------------- launch ----------------
extern "C" void kernel_launch(void* const* d_in, const int* in_sizes, int n_in,
                              void* d_out, int out_size) {
    const float* x     = (const float*)d_in[0];
    const float* W     = (const float*)d_in[1];
    const float* b     = (const float*)d_in[2];
    const float* lin_w = (const float*)d_in[3];
    const float* lin_b = (const float*)d_in[4];
    const int*   ei    = (const int*)d_in[5];
    const int*   batch = (const int*)d_in[6];
    float* out = (float*)d_out;

    float *xw, *agg, *invd0, *invd1;
    int *deg0, *deg1, *ptr0, *ptr1, *cur0, *cur1;
    int2 *ce0, *ce1;
    cudaGetSymbolAddress((void**)&xw,    g_xw);
    cudaGetSymbolAddress((void**)&agg,   g_agg);
    cudaGetSymbolAddress((void**)&invd0, g_invd0);
    cudaGetSymbolAddress((void**)&invd1, g_invd1);
    cudaGetSymbolAddress((void**)&deg0,  g_deg0);
    cudaGetSymbolAddress((void**)&deg1,  g_deg1);
    cudaGetSymbolAddress((void**)&ptr0,  g_ptr0);
    cudaGetSymbolAddress((void**)&ptr1,  g_ptr1);
    cudaGetSymbolAddress((void**)&cur0,  g_cur0);
    cudaGetSymbolAddress((void**)&cur1,  g_cur1);
    cudaGetSymbolAddress((void**)&ce0,   g_ce0);
    cudaGetSymbolAddress((void**)&ce1,   g_ce1);

    const int* src0 = ei + 0 * EE;
    const int* dst0 = ei + 1 * EE;
    const int* src1 = ei + 2 * EE;
    const int* dst1 = ei + 3 * EE;

    const int TB = 256;
    int nodeBlocks = (NN + TB - 1) / TB;
    int edgeBlocks = (EE + TB - 1) / TB;
    int warpBlocks = (NN * 32 + TB - 1) / TB;
    dim3 gemmGrid((NN + 127) / 128, 2);

    // CSR build (per call; reused across both layers)
    zero_all<<<nodeBlocks, TB>>>();
    hist<<<edgeBlocks, TB>>>(dst0, deg0);
    hist<<<edgeBlocks, TB>>>(dst1, deg1);
    make_invd<<<nodeBlocks, TB>>>();
    exscan<<<1, 1024>>>(deg0, ptr0, cur0);
    exscan<<<1, 1024>>>(deg1, ptr1, cur1);
    csr_fill<<<edgeBlocks, TB>>>(src0, dst0, invd0, cur0, ce0);
    csr_fill<<<edgeBlocks, TB>>>(src1, dst1, invd1, cur1, ce1);

    // layer 0
    gemm_dual<false><<<gemmGrid, 256>>>(x, W + 0 * 2 * DD * DD, xw);
    gather_both<<<warpBlocks, TB>>>(xw, b + 0 * 2 * DD, agg);

    // layer 1 (relu fused into GEMM A-load)
    gemm_dual<true><<<gemmGrid, 256>>>(agg, W + 1 * 2 * DD * DD, xw);
    gather_both<<<warpBlocks, TB>>>(xw, b + 1 * 2 * DD, agg);

    // pooling + classifier
    count_batch<<<nodeBlocks, TB>>>(batch);
    scan64<<<1, 32>>>();
    dim3 pg(GG, 8);
    pool_partial<<<pg, DD>>>(agg);
    final_linear<<<1, GG * CC>>>(lin_w, lin_b, out);
}

// round 3
// speedup vs baseline: 1.4411x; 1.1445x over previous
#include <cuda_runtime.h>

#define NN 50000
#define EE 800000
#define DD 128
#define GG 64
#define CC 8

// ---------------- static scratch ----------------
__device__ float g_xw[NN * 256];        // [N, 256]: cols 0-127 rel0, 128-255 rel1
__device__ float g_agg[NN * DD];
__device__ float g_invd0[NN];
__device__ float g_invd1[NN];
__device__ int   g_deg0[NN];
__device__ int   g_deg1[NN];
__device__ int   g_ptr0[NN + 1];
__device__ int   g_ptr1[NN + 1];
__device__ int   g_cur0[NN];
__device__ int   g_cur1[NN];
__device__ int2  g_ce0[EE];
__device__ int2  g_ce1[EE];
__device__ float g_pooled[GG * DD];
__device__ int   g_counts[GG];
__device__ int   g_offsets[GG + 1];

// ---------------- setup (fused) ----------------
__global__ void zero_all() {
    int i = blockIdx.x * blockDim.x + threadIdx.x;
    if (i < NN) { g_deg0[i] = 0; g_deg1[i] = 0; }
    if (i < GG) g_counts[i] = 0;
    if (i < GG * DD) g_pooled[i] = 0.0f;
}

__global__ void hist_both(const int* __restrict__ ei) {
    int t = blockIdx.x * blockDim.x + threadIdx.x;
    if (t < EE)            atomicAdd(&g_deg0[ei[EE + t]], 1);           // dst0
    else if (t < 2 * EE)   atomicAdd(&g_deg1[ei[3 * EE + (t - EE)]], 1); // dst1
}

__global__ void make_invd() {
    int i = blockIdx.x * blockDim.x + threadIdx.x;
    if (i < NN) {
        g_invd0[i] = rsqrtf((float)(g_deg0[i] + 1));
        g_invd1[i] = rsqrtf((float)(g_deg1[i] + 1));
    }
}

__global__ void exscan2() {
    const int* __restrict__ cnt = blockIdx.x ? g_deg1 : g_deg0;
    int* __restrict__ ptr = blockIdx.x ? g_ptr1 : g_ptr0;
    int* __restrict__ cur = blockIdx.x ? g_cur1 : g_cur0;
    __shared__ int part[1024];
    int tid = threadIdx.x;
    const int PER = (NN + 1023) / 1024;
    int start = tid * PER;
    int end = min(NN, start + PER);
    int s = 0;
    for (int i = start; i < end; ++i) s += cnt[i];
    part[tid] = s;
    __syncthreads();
    for (int off = 1; off < 1024; off <<= 1) {
        int v = (tid >= off) ? part[tid - off] : 0;
        __syncthreads();
        part[tid] += v;
        __syncthreads();
    }
    int base = (tid == 0) ? 0 : part[tid - 1];
    for (int i = start; i < end; ++i) {
        ptr[i] = base; cur[i] = base;
        base += cnt[i];
    }
    if (tid == 1023) ptr[NN] = part[1023];
}

__global__ void csr_fill_both(const int* __restrict__ ei) {
    int t = blockIdx.x * blockDim.x + threadIdx.x;
    if (t < EE) {
        int s = ei[t], d = ei[EE + t];
        int slot = atomicAdd(&g_cur0[d], 1);
        int2 p; p.x = s; p.y = __float_as_int(g_invd0[s] * g_invd0[d]);
        g_ce0[slot] = p;
    } else if (t < 2 * EE) {
        int e = t - EE;
        int s = ei[2 * EE + e], d = ei[3 * EE + e];
        int slot = atomicAdd(&g_cur1[d], 1);
        int2 p; p.x = s; p.y = __float_as_int(g_invd1[s] * g_invd1[d]);
        g_ce1[slot] = p;
    }
}

// ---------------- tensor-core GEMM (3xTF32): out[N,256] = act(A)[N,128] @ W[rel] ----------------
// CTA: 128 rows x 128 cols, K chunked by 16. 256 threads = 8 warps (2x4 warp grid, 64x32/warp).
__device__ __forceinline__ unsigned f2tf32(float v) {
    unsigned r;
    asm("cvt.rna.tf32.f32 %0, %1;" : "=r"(r) : "f"(v));
    return r;
}
__device__ __forceinline__ void mma_tf32(float* c, const unsigned* a, const unsigned* b) {
    asm volatile(
        "mma.sync.aligned.m16n8k8.row.col.f32.tf32.tf32.f32 "
        "{%0,%1,%2,%3}, {%4,%5,%6,%7}, {%8,%9}, {%0,%1,%2,%3};"
        : "+f"(c[0]), "+f"(c[1]), "+f"(c[2]), "+f"(c[3])
        : "r"(a[0]), "r"(a[1]), "r"(a[2]), "r"(a[3]), "r"(b[0]), "r"(b[1]));
}

#define SSTR 136   // smem row stride (floats): bank = (8k + col) % 32, conflict-free frags

template <bool RELU>
__global__ void __launch_bounds__(256, 2)
gemm_tc(const float* __restrict__ A, const float* __restrict__ Wl,
        float* __restrict__ out) {
    __shared__ unsigned sAhi[16][SSTR], sAlo[16][SSTR];
    __shared__ unsigned sBhi[16][SSTR], sBlo[16][SSTR];

    const int rel = blockIdx.y;
    const float* Wr = Wl + rel * DD * DD;
    const int rowBase = blockIdx.x * 128;
    const int tid = threadIdx.x;
    const int warp = tid >> 5, lane = tid & 31;
    const int wm = warp >> 2, wn = warp & 3;      // warp tile: rows wm*64, cols wn*32
    const int lrow = lane >> 2;                    // 0..7
    const int lk = lane & 3;                       // 0..3

    float acc[4][4][4];
    #pragma unroll
    for (int i = 0; i < 4; ++i)
        #pragma unroll
        for (int j = 0; j < 4; ++j)
            #pragma unroll
            for (int q = 0; q < 4; ++q) acc[i][j][q] = 0.0f;

    const int alr = tid >> 1;            // A row 0..127
    const int alk = (tid & 1) * 8;       // A k offset 0 or 8

    for (int k0 = 0; k0 < DD; k0 += 16) {
        // ---- load & split A tile (128 x 16) ----
        {
            int gr = rowBase + alr;
            float4 v0 = make_float4(0.f, 0.f, 0.f, 0.f), v1 = v0;
            if (gr < NN) {
                const float* ap = A + (size_t)gr * DD + k0 + alk;
                v0 = *reinterpret_cast<const float4*>(ap);
                v1 = *reinterpret_cast<const float4*>(ap + 4);
            }
            if (RELU) {
                v0.x = fmaxf(v0.x, 0.f); v0.y = fmaxf(v0.y, 0.f);
                v0.z = fmaxf(v0.z, 0.f); v0.w = fmaxf(v0.w, 0.f);
                v1.x = fmaxf(v1.x, 0.f); v1.y = fmaxf(v1.y, 0.f);
                v1.z = fmaxf(v1.z, 0.f); v1.w = fmaxf(v1.w, 0.f);
            }
            float va[8] = {v0.x, v0.y, v0.z, v0.w, v1.x, v1.y, v1.z, v1.w};
            #pragma unroll
            for (int j = 0; j < 8; ++j) {
                unsigned hi = f2tf32(va[j]);
                float lo = va[j] - __uint_as_float(hi);
                sAhi[alk + j][alr] = hi;
                sAlo[alk + j][alr] = f2tf32(lo);
            }
        }
        // ---- load & split B tile (16 x 128) ----
        #pragma unroll
        for (int i = 0; i < 2; ++i) {
            int idx = tid + i * 256;          // 0..511
            int k = idx >> 5, c = (idx & 31) * 4;
            float4 w = *reinterpret_cast<const float4*>(Wr + (k0 + k) * DD + c);
            float wa[4] = {w.x, w.y, w.z, w.w};
            #pragma unroll
            for (int j = 0; j < 4; ++j) {
                unsigned hi = f2tf32(wa[j]);
                float lo = wa[j] - __uint_as_float(hi);
                sBhi[k][c + j] = hi;
                sBlo[k][c + j] = f2tf32(lo);
            }
        }
        __syncthreads();

        // ---- 2 k8 steps ----
        #pragma unroll
        for (int ks = 0; ks < 2; ++ks) {
            const int kk = ks * 8;
            unsigned ua[4][4];   // A frags (hi first, later overwritten by lo)
            unsigned ubh[4][2], ubl[4][2];
            #pragma unroll
            for (int mt = 0; mt < 4; ++mt) {
                int rm = wm * 64 + mt * 16 + lrow;
                ua[mt][0] = sAhi[kk + lk][rm];
                ua[mt][1] = sAhi[kk + lk][rm + 8];
                ua[mt][2] = sAhi[kk + lk + 4][rm];
                ua[mt][3] = sAhi[kk + lk + 4][rm + 8];
            }
            #pragma unroll
            for (int nt = 0; nt < 4; ++nt) {
                int cn = wn * 32 + nt * 8 + lrow;
                ubh[nt][0] = sBhi[kk + lk][cn];
                ubh[nt][1] = sBhi[kk + lk + 4][cn];
                ubl[nt][0] = sBlo[kk + lk][cn];
                ubl[nt][1] = sBlo[kk + lk + 4][cn];
            }
            // hi x hi
            #pragma unroll
            for (int mt = 0; mt < 4; ++mt)
                #pragma unroll
                for (int nt = 0; nt < 4; ++nt)
                    mma_tf32(acc[mt][nt], ua[mt], ubh[nt]);
            // hi x lo
            #pragma unroll
            for (int mt = 0; mt < 4; ++mt)
                #pragma unroll
                for (int nt = 0; nt < 4; ++nt)
                    mma_tf32(acc[mt][nt], ua[mt], ubl[nt]);
            // lo x hi
            #pragma unroll
            for (int mt = 0; mt < 4; ++mt) {
                int rm = wm * 64 + mt * 16 + lrow;
                ua[mt][0] = sAlo[kk + lk][rm];
                ua[mt][1] = sAlo[kk + lk][rm + 8];
                ua[mt][2] = sAlo[kk + lk + 4][rm];
                ua[mt][3] = sAlo[kk + lk + 4][rm + 8];
            }
            #pragma unroll
            for (int mt = 0; mt < 4; ++mt)
                #pragma unroll
                for (int nt = 0; nt < 4; ++nt)
                    mma_tf32(acc[mt][nt], ua[mt], ubh[nt]);
        }
        __syncthreads();
    }

    // ---- epilogue ----
    #pragma unroll
    for (int mt = 0; mt < 4; ++mt) {
        int r0 = rowBase + wm * 64 + mt * 16 + lrow;
        #pragma unroll
        for (int nt = 0; nt < 4; ++nt) {
            int cn = rel * 128 + wn * 32 + nt * 8 + 2 * lk;
            if (r0 < NN)
                *reinterpret_cast<float2*>(out + (size_t)r0 * 256 + cn) =
                    make_float2(acc[mt][nt][0], acc[mt][nt][1]);
            if (r0 + 8 < NN)
                *reinterpret_cast<float2*>(out + (size_t)(r0 + 8) * 256 + cn) =
                    make_float2(acc[mt][nt][2], acc[mt][nt][3]);
        }
    }
}

// ---------------- fused aggregation (CSR gather, both relations) ----------------
__global__ void gather_both(const float* __restrict__ xw,
                            const float* __restrict__ b_l,
                            float* __restrict__ agg) {
    int t = blockIdx.x * blockDim.x + threadIdx.x;
    int i = t >> 5;
    int lane = t & 31;
    if (i >= NN) return;
    int c4 = lane * 4;

    float s0 = g_invd0[i]; s0 *= s0;
    float s1 = g_invd1[i]; s1 *= s1;
    const float4* row = reinterpret_cast<const float4*>(xw + (size_t)i * 256);
    float4 v0 = row[lane];
    float4 v1 = row[32 + lane];
    float4 acc;
    acc.x = fmaf(v0.x, s0, v1.x * s1) + b_l[c4 + 0] + b_l[DD + c4 + 0];
    acc.y = fmaf(v0.y, s0, v1.y * s1) + b_l[c4 + 1] + b_l[DD + c4 + 1];
    acc.z = fmaf(v0.z, s0, v1.z * s1) + b_l[c4 + 2] + b_l[DD + c4 + 2];
    acc.w = fmaf(v0.w, s0, v1.w * s1) + b_l[c4 + 3] + b_l[DD + c4 + 3];

    {
        int b0 = g_ptr0[i], e0 = g_ptr0[i + 1];
        int tt = b0;
        for (; tt + 1 < e0; tt += 2) {
            int2 pA = g_ce0[tt], pB = g_ce0[tt + 1];
            float wA = __int_as_float(pA.y), wB = __int_as_float(pB.y);
            float4 vA = *reinterpret_cast<const float4*>(xw + (size_t)pA.x * 256 + c4);
            float4 vB = *reinterpret_cast<const float4*>(xw + (size_t)pB.x * 256 + c4);
            acc.x = fmaf(wA, vA.x, fmaf(wB, vB.x, acc.x));
            acc.y = fmaf(wA, vA.y, fmaf(wB, vB.y, acc.y));
            acc.z = fmaf(wA, vA.z, fmaf(wB, vB.z, acc.z));
            acc.w = fmaf(wA, vA.w, fmaf(wB, vB.w, acc.w));
        }
        if (tt < e0) {
            int2 p = g_ce0[tt];
            float w = __int_as_float(p.y);
            float4 v = *reinterpret_cast<const float4*>(xw + (size_t)p.x * 256 + c4);
            acc.x = fmaf(w, v.x, acc.x); acc.y = fmaf(w, v.y, acc.y);
            acc.z = fmaf(w, v.z, acc.z); acc.w = fmaf(w, v.w, acc.w);
        }
    }
    {
        int b1 = g_ptr1[i], e1 = g_ptr1[i + 1];
        int tt = b1;
        for (; tt + 1 < e1; tt += 2) {
            int2 pA = g_ce1[tt], pB = g_ce1[tt + 1];
            float wA = __int_as_float(pA.y), wB = __int_as_float(pB.y);
            float4 vA = *reinterpret_cast<const float4*>(xw + (size_t)pA.x * 256 + 128 + c4);
            float4 vB = *reinterpret_cast<const float4*>(xw + (size_t)pB.x * 256 + 128 + c4);
            acc.x = fmaf(wA, vA.x, fmaf(wB, vB.x, acc.x));
            acc.y = fmaf(wA, vA.y, fmaf(wB, vB.y, acc.y));
            acc.z = fmaf(wA, vA.z, fmaf(wB, vB.z, acc.z));
            acc.w = fmaf(wA, vA.w, fmaf(wB, vB.w, acc.w));
        }
        if (tt < e1) {
            int2 p = g_ce1[tt];
            float w = __int_as_float(p.y);
            float4 v = *reinterpret_cast<const float4*>(xw + (size_t)p.x * 256 + 128 + c4);
            acc.x = fmaf(w, v.x, acc.x); acc.y = fmaf(w, v.y, acc.y);
            acc.z = fmaf(w, v.z, acc.z); acc.w = fmaf(w, v.w, acc.w);
        }
    }
    *reinterpret_cast<float4*>(agg + (size_t)i * DD + c4) = acc;
}

// ---------------- pooling + classifier ----------------
__global__ void count_batch(const int* __restrict__ batch) {
    int i = blockIdx.x * blockDim.x + threadIdx.x;
    if (i < NN) atomicAdd(&g_counts[batch[i]], 1);
}

__global__ void scan64() {
    if (threadIdx.x == 0) {
        int acc = 0;
        for (int g = 0; g < GG; ++g) { g_offsets[g] = acc; acc += g_counts[g]; }
        g_offsets[GG] = acc;
    }
}

__global__ void pool_partial(const float* __restrict__ h) {
    int g = blockIdx.x;
    int chunk = blockIdx.y;
    int d = threadIdx.x;
    int start = g_offsets[g], end = g_offsets[g + 1];
    int n = end - start;
    int per = (n + (int)gridDim.y - 1) / (int)gridDim.y;
    int s = start + chunk * per;
    int e = min(end, s + per);
    float acc = 0.0f;
    for (int i = s; i < e; ++i) acc += h[(size_t)i * DD + d];
    if (s < e) atomicAdd(&g_pooled[g * DD + d], acc);
}

__global__ void final_linear(const float* __restrict__ lin_w,
                             const float* __restrict__ lin_b,
                             float* __restrict__ out) {
    int t = threadIdx.x;            // 512 = GG*CC
    int g = t >> 3, c = t & 7;
    float cnt = (float)max(g_counts[g], 1);
    float acc = 0.0f;
    #pragma unroll 16
    for (int d = 0; d < DD; ++d) acc += g_pooled[g * DD + d] * lin_w[d * CC + c];
    out[g * CC + c] = acc / cnt + lin_b[c];
}

// ---------------- launch ----------------
extern "C" void kernel_launch(void* const* d_in, const int* in_sizes, int n_in,
                              void* d_out, int out_size) {
    const float* x     = (const float*)d_in[0];
    const float* W     = (const float*)d_in[1];
    const float* b     = (const float*)d_in[2];
    const float* lin_w = (const float*)d_in[3];
    const float* lin_b = (const float*)d_in[4];
    const int*   ei    = (const int*)d_in[5];
    const int*   batch = (const int*)d_in[6];
    float* out = (float*)d_out;

    float *xw, *agg;
    cudaGetSymbolAddress((void**)&xw,  g_xw);
    cudaGetSymbolAddress((void**)&agg, g_agg);

    const int TB = 256;
    int nodeBlocks  = (NN + TB - 1) / TB;
    int edge2Blocks = (2 * EE + TB - 1) / TB;
    int warpBlocks  = (NN * 32 + TB - 1) / TB;
    dim3 gemmGrid((NN + 127) / 128, 2);

    // setup — exactly 5 launches so the layer-0 GEMM is ncu's "-s 5" target
    zero_all<<<nodeBlocks, TB>>>();                 // 0
    hist_both<<<edge2Blocks, TB>>>(ei);             // 1
    make_invd<<<nodeBlocks, TB>>>();                // 2
    exscan2<<<2, 1024>>>();                         // 3
    csr_fill_both<<<edge2Blocks, TB>>>(ei);         // 4

    // layer 0
    gemm_tc<false><<<gemmGrid, 256>>>(x, W + 0 * 2 * DD * DD, xw);   // 5 (profiled)
    gather_both<<<warpBlocks, TB>>>(xw, b + 0 * 2 * DD, agg);        // 6

    // layer 1
    gemm_tc<true><<<gemmGrid, 256>>>(agg, W + 1 * 2 * DD * DD, xw);  // 7
    gather_both<<<warpBlocks, TB>>>(xw, b + 1 * 2 * DD, agg);        // 8

    // pooling + classifier
    count_batch<<<nodeBlocks, TB>>>(batch);
    scan64<<<1, 32>>>();
    dim3 pg(GG, 8);
    pool_partial<<<pg, DD>>>(agg);
    final_linear<<<1, GG * CC>>>(lin_w, lin_b, out);
}

// round 5
// speedup vs baseline: 2.0564x; 1.4269x over previous
#include <cuda_runtime.h>
#include <cuda_fp16.h>

#define NN 50000
#define EE 800000
#define DD 128
#define GG 64
#define CC 8

#define SCAN_TB 256
#define SCAN_BLOCKS ((NN + SCAN_TB - 1) / SCAN_TB)   // 196

// ---------------- static scratch ----------------
__device__ __half g_xw[NN * 256];       // [N, 256] fp16: cols 0-127 rel0, 128-255 rel1
__device__ float g_agg[NN * DD];
__device__ float g_invd0[NN];
__device__ float g_invd1[NN];
__device__ int   g_deg0[NN];
__device__ int   g_deg1[NN];
__device__ int   g_ptr0[NN + 1];
__device__ int   g_ptr1[NN + 1];
__device__ int   g_cur0[NN];
__device__ int   g_cur1[NN];
__device__ int2  g_ce0[EE];
__device__ int2  g_ce1[EE];
__device__ int   g_bsum[2][SCAN_BLOCKS];
__device__ float g_pooled[GG * DD];
__device__ int   g_counts[GG];
__device__ int   g_offsets[GG + 1];

// ---------------- setup ----------------
__global__ void zero_all() {
    int i = blockIdx.x * blockDim.x + threadIdx.x;
    if (i < NN) { g_deg0[i] = 0; g_deg1[i] = 0; }
    if (i < GG) g_counts[i] = 0;
    if (i < GG * DD) g_pooled[i] = 0.0f;
}

__global__ void hist_both(const int* __restrict__ ei) {
    int t = blockIdx.x * blockDim.x + threadIdx.x;
    if (t < EE)            atomicAdd(&g_deg0[ei[EE + t]], 1);
    else if (t < 2 * EE)   atomicAdd(&g_deg1[ei[3 * EE + (t - EE)]], 1);
}

__global__ void make_invd() {
    int i = blockIdx.x * blockDim.x + threadIdx.x;
    if (i < NN) {
        g_invd0[i] = rsqrtf((float)(g_deg0[i] + 1));
        g_invd1[i] = rsqrtf((float)(g_deg1[i] + 1));
    }
}

// block-exclusive prescan; emits per-block totals
__global__ void scan_p1() {
    int rel = blockIdx.y;
    const int* __restrict__ cnt = rel ? g_deg1 : g_deg0;
    int* __restrict__ ptr = rel ? g_ptr1 : g_ptr0;
    int i = blockIdx.x * SCAN_TB + threadIdx.x;
    int v = (i < NN) ? cnt[i] : 0;
    int lane = threadIdx.x & 31, w = threadIdx.x >> 5;
    int incl = v;
    #pragma unroll
    for (int o = 1; o < 32; o <<= 1) {
        int t = __shfl_up_sync(0xffffffffu, incl, o);
        if (lane >= o) incl += t;
    }
    __shared__ int wsum[8];
    if (lane == 31) wsum[w] = incl;
    __syncthreads();
    if (w == 0) {
        int s = (lane < 8) ? wsum[lane] : 0;
        #pragma unroll
        for (int o = 1; o < 8; o <<= 1) {
            int t = __shfl_up_sync(0xffffffffu, s, o);
            if (lane >= o) s += t;
        }
        if (lane < 8) wsum[lane] = s;    // inclusive warp prefix
    }
    __syncthreads();
    int base = (w > 0) ? wsum[w - 1] : 0;
    if (i < NN) ptr[i] = base + incl - v;
    if (threadIdx.x == SCAN_TB - 1) g_bsum[rel][blockIdx.x] = base + incl;
}

// exclusive scan of the 196 block sums (per relation)
__global__ void scan_p2() {
    int rel = blockIdx.x;
    int tid = threadIdx.x;
    int v = (tid < SCAN_BLOCKS) ? g_bsum[rel][tid] : 0;
    int lane = tid & 31, w = tid >> 5;
    int incl = v;
    #pragma unroll
    for (int o = 1; o < 32; o <<= 1) {
        int t = __shfl_up_sync(0xffffffffu, incl, o);
        if (lane >= o) incl += t;
    }
    __shared__ int wsum[8];
    if (lane == 31) wsum[w] = incl;
    __syncthreads();
    if (w == 0) {
        int s = (lane < 8) ? wsum[lane] : 0;
        #pragma unroll
        for (int o = 1; o < 8; o <<= 1) {
            int t = __shfl_up_sync(0xffffffffu, s, o);
            if (lane >= o) s += t;
        }
        if (lane < 8) wsum[lane] = s;
    }
    __syncthreads();
    int base = (w > 0) ? wsum[w - 1] : 0;
    if (tid < SCAN_BLOCKS) g_bsum[rel][tid] = base + incl - v;
}

// add back block offsets; init cursors; set ptr[NN]
__global__ void scan_p3() {
    int rel = blockIdx.y;
    int* __restrict__ ptr = rel ? g_ptr1 : g_ptr0;
    int* __restrict__ cur = rel ? g_cur1 : g_cur0;
    int i = blockIdx.x * SCAN_TB + threadIdx.x;
    if (i < NN) {
        int p = ptr[i] + g_bsum[rel][blockIdx.x];
        ptr[i] = p; cur[i] = p;
    }
    if (i == 0) ptr[NN] = EE;
}

__global__ void csr_fill_both(const int* __restrict__ ei) {
    int t = blockIdx.x * blockDim.x + threadIdx.x;
    if (t < EE) {
        int s = ei[t], d = ei[EE + t];
        int slot = atomicAdd(&g_cur0[d], 1);
        int2 p; p.x = s; p.y = __float_as_int(g_invd0[s] * g_invd0[d]);
        g_ce0[slot] = p;
    } else if (t < 2 * EE) {
        int e = t - EE;
        int s = ei[2 * EE + e], d = ei[3 * EE + e];
        int slot = atomicAdd(&g_cur1[d], 1);
        int2 p; p.x = s; p.y = __float_as_int(g_invd1[s] * g_invd1[d]);
        g_ce1[slot] = p;
    }
}

// ---------------- tensor-core GEMM (3xTF32) -> fp16 out ----------------
__device__ __forceinline__ unsigned f2tf32(float v) {
    unsigned r;
    asm("cvt.rna.tf32.f32 %0, %1;" : "=r"(r) : "f"(v));
    return r;
}
__device__ __forceinline__ void mma_tf32(float* c, const unsigned* a, const unsigned* b) {
    asm volatile(
        "mma.sync.aligned.m16n8k8.row.col.f32.tf32.tf32.f32 "
        "{%0,%1,%2,%3}, {%4,%5,%6,%7}, {%8,%9}, {%0,%1,%2,%3};"
        : "+f"(c[0]), "+f"(c[1]), "+f"(c[2]), "+f"(c[3])
        : "r"(a[0]), "r"(a[1]), "r"(a[2]), "r"(a[3]), "r"(b[0]), "r"(b[1]));
}

#define SSTR 136

template <bool RELU>
__global__ void __launch_bounds__(256, 2)
gemm_tc(const float* __restrict__ A, const float* __restrict__ Wl,
        __half* __restrict__ out) {
    __shared__ unsigned sAhi[16][SSTR], sAlo[16][SSTR];
    __shared__ unsigned sBhi[16][SSTR], sBlo[16][SSTR];

    const int rel = blockIdx.y;
    const float* Wr = Wl + rel * DD * DD;
    const int rowBase = blockIdx.x * 128;
    const int tid = threadIdx.x;
    const int warp = tid >> 5, lane = tid & 31;
    const int wm = warp >> 2, wn = warp & 3;
    const int lrow = lane >> 2;
    const int lk = lane & 3;

    float acc[4][4][4];
    #pragma unroll
    for (int i = 0; i < 4; ++i)
        #pragma unroll
        for (int j = 0; j < 4; ++j)
            #pragma unroll
            for (int q = 0; q < 4; ++q) acc[i][j][q] = 0.0f;

    const int alr = tid >> 1;
    const int alk = (tid & 1) * 8;

    for (int k0 = 0; k0 < DD; k0 += 16) {
        {
            int gr = rowBase + alr;
            float4 v0 = make_float4(0.f, 0.f, 0.f, 0.f), v1 = v0;
            if (gr < NN) {
                const float* ap = A + (size_t)gr * DD + k0 + alk;
                v0 = *reinterpret_cast<const float4*>(ap);
                v1 = *reinterpret_cast<const float4*>(ap + 4);
            }
            if (RELU) {
                v0.x = fmaxf(v0.x, 0.f); v0.y = fmaxf(v0.y, 0.f);
                v0.z = fmaxf(v0.z, 0.f); v0.w = fmaxf(v0.w, 0.f);
                v1.x = fmaxf(v1.x, 0.f); v1.y = fmaxf(v1.y, 0.f);
                v1.z = fmaxf(v1.z, 0.f); v1.w = fmaxf(v1.w, 0.f);
            }
            float va[8] = {v0.x, v0.y, v0.z, v0.w, v1.x, v1.y, v1.z, v1.w};
            #pragma unroll
            for (int j = 0; j < 8; ++j) {
                unsigned hi = f2tf32(va[j]);
                float lo = va[j] - __uint_as_float(hi);
                sAhi[alk + j][alr] = hi;
                sAlo[alk + j][alr] = f2tf32(lo);
            }
        }
        #pragma unroll
        for (int i = 0; i < 2; ++i) {
            int idx = tid + i * 256;
            int k = idx >> 5, c = (idx & 31) * 4;
            float4 w = *reinterpret_cast<const float4*>(Wr + (k0 + k) * DD + c);
            float wa[4] = {w.x, w.y, w.z, w.w};
            #pragma unroll
            for (int j = 0; j < 4; ++j) {
                unsigned hi = f2tf32(wa[j]);
                float lo = wa[j] - __uint_as_float(hi);
                sBhi[k][c + j] = hi;
                sBlo[k][c + j] = f2tf32(lo);
            }
        }
        __syncthreads();

        #pragma unroll
        for (int ks = 0; ks < 2; ++ks) {
            const int kk = ks * 8;
            unsigned ua[4][4];
            unsigned ubh[4][2], ubl[4][2];
            #pragma unroll
            for (int mt = 0; mt < 4; ++mt) {
                int rm = wm * 64 + mt * 16 + lrow;
                ua[mt][0] = sAhi[kk + lk][rm];
                ua[mt][1] = sAhi[kk + lk][rm + 8];
                ua[mt][2] = sAhi[kk + lk + 4][rm];
                ua[mt][3] = sAhi[kk + lk + 4][rm + 8];
            }
            #pragma unroll
            for (int nt = 0; nt < 4; ++nt) {
                int cn = wn * 32 + nt * 8 + lrow;
                ubh[nt][0] = sBhi[kk + lk][cn];
                ubh[nt][1] = sBhi[kk + lk + 4][cn];
                ubl[nt][0] = sBlo[kk + lk][cn];
                ubl[nt][1] = sBlo[kk + lk + 4][cn];
            }
            #pragma unroll
            for (int mt = 0; mt < 4; ++mt)
                #pragma unroll
                for (int nt = 0; nt < 4; ++nt)
                    mma_tf32(acc[mt][nt], ua[mt], ubh[nt]);
            #pragma unroll
            for (int mt = 0; mt < 4; ++mt)
                #pragma unroll
                for (int nt = 0; nt < 4; ++nt)
                    mma_tf32(acc[mt][nt], ua[mt], ubl[nt]);
            #pragma unroll
            for (int mt = 0; mt < 4; ++mt) {
                int rm = wm * 64 + mt * 16 + lrow;
                ua[mt][0] = sAlo[kk + lk][rm];
                ua[mt][1] = sAlo[kk + lk][rm + 8];
                ua[mt][2] = sAlo[kk + lk + 4][rm];
                ua[mt][3] = sAlo[kk + lk + 4][rm + 8];
            }
            #pragma unroll
            for (int mt = 0; mt < 4; ++mt)
                #pragma unroll
                for (int nt = 0; nt < 4; ++nt)
                    mma_tf32(acc[mt][nt], ua[mt], ubh[nt]);
        }
        __syncthreads();
    }

    // epilogue: convert to fp16
    #pragma unroll
    for (int mt = 0; mt < 4; ++mt) {
        int r0 = rowBase + wm * 64 + mt * 16 + lrow;
        #pragma unroll
        for (int nt = 0; nt < 4; ++nt) {
            int cn = rel * 128 + wn * 32 + nt * 8 + 2 * lk;
            if (r0 < NN)
                *reinterpret_cast<__half2*>(out + (size_t)r0 * 256 + cn) =
                    __floats2half2_rn(acc[mt][nt][0], acc[mt][nt][1]);
            if (r0 + 8 < NN)
                *reinterpret_cast<__half2*>(out + (size_t)(r0 + 8) * 256 + cn) =
                    __floats2half2_rn(acc[mt][nt][2], acc[mt][nt][3]);
        }
    }
}

// ---------------- fused aggregation (CSR gather, fp16 source) ----------------
__device__ __forceinline__ float4 ldh4(const __half* p) {
    uint2 u = *reinterpret_cast<const uint2*>(p);
    float2 fa = __half22float2(*reinterpret_cast<__half2*>(&u.x));
    float2 fb = __half22float2(*reinterpret_cast<__half2*>(&u.y));
    return make_float4(fa.x, fa.y, fb.x, fb.y);
}

__global__ void gather_both(const __half* __restrict__ xw,
                            const float* __restrict__ b_l,
                            float* __restrict__ agg) {
    int t = blockIdx.x * blockDim.x + threadIdx.x;
    int i = t >> 5;
    int lane = t & 31;
    if (i >= NN) return;
    int c4 = lane * 4;

    float s0 = g_invd0[i]; s0 *= s0;
    float s1 = g_invd1[i]; s1 *= s1;
    float4 v0 = ldh4(xw + (size_t)i * 256 + c4);
    float4 v1 = ldh4(xw + (size_t)i * 256 + 128 + c4);
    float4 acc;
    acc.x = fmaf(v0.x, s0, v1.x * s1) + b_l[c4 + 0] + b_l[DD + c4 + 0];
    acc.y = fmaf(v0.y, s0, v1.y * s1) + b_l[c4 + 1] + b_l[DD + c4 + 1];
    acc.z = fmaf(v0.z, s0, v1.z * s1) + b_l[c4 + 2] + b_l[DD + c4 + 2];
    acc.w = fmaf(v0.w, s0, v1.w * s1) + b_l[c4 + 3] + b_l[DD + c4 + 3];

    {
        int b0 = g_ptr0[i], e0 = g_ptr0[i + 1];
        int tt = b0;
        for (; tt + 1 < e0; tt += 2) {
            int2 pA = g_ce0[tt], pB = g_ce0[tt + 1];
            float wA = __int_as_float(pA.y), wB = __int_as_float(pB.y);
            float4 vA = ldh4(xw + (size_t)pA.x * 256 + c4);
            float4 vB = ldh4(xw + (size_t)pB.x * 256 + c4);
            acc.x = fmaf(wA, vA.x, fmaf(wB, vB.x, acc.x));
            acc.y = fmaf(wA, vA.y, fmaf(wB, vB.y, acc.y));
            acc.z = fmaf(wA, vA.z, fmaf(wB, vB.z, acc.z));
            acc.w = fmaf(wA, vA.w, fmaf(wB, vB.w, acc.w));
        }
        if (tt < e0) {
            int2 p = g_ce0[tt];
            float w = __int_as_float(p.y);
            float4 v = ldh4(xw + (size_t)p.x * 256 + c4);
            acc.x = fmaf(w, v.x, acc.x); acc.y = fmaf(w, v.y, acc.y);
            acc.z = fmaf(w, v.z, acc.z); acc.w = fmaf(w, v.w, acc.w);
        }
    }
    {
        int b1 = g_ptr1[i], e1 = g_ptr1[i + 1];
        int tt = b1;
        for (; tt + 1 < e1; tt += 2) {
            int2 pA = g_ce1[tt], pB = g_ce1[tt + 1];
            float wA = __int_as_float(pA.y), wB = __int_as_float(pB.y);
            float4 vA = ldh4(xw + (size_t)pA.x * 256 + 128 + c4);
            float4 vB = ldh4(xw + (size_t)pB.x * 256 + 128 + c4);
            acc.x = fmaf(wA, vA.x, fmaf(wB, vB.x, acc.x));
            acc.y = fmaf(wA, vA.y, fmaf(wB, vB.y, acc.y));
            acc.z = fmaf(wA, vA.z, fmaf(wB, vB.z, acc.z));
            acc.w = fmaf(wA, vA.w, fmaf(wB, vB.w, acc.w));
        }
        if (tt < e1) {
            int2 p = g_ce1[tt];
            float w = __int_as_float(p.y);
            float4 v = ldh4(xw + (size_t)p.x * 256 + 128 + c4);
            acc.x = fmaf(w, v.x, acc.x); acc.y = fmaf(w, v.y, acc.y);
            acc.z = fmaf(w, v.z, acc.z); acc.w = fmaf(w, v.w, acc.w);
        }
    }
    *reinterpret_cast<float4*>(agg + (size_t)i * DD + c4) = acc;
}

// ---------------- pooling + classifier ----------------
__global__ void count_batch(const int* __restrict__ batch) {
    int i = blockIdx.x * blockDim.x + threadIdx.x;
    if (i < NN) atomicAdd(&g_counts[batch[i]], 1);
}

__global__ void scan64() {
    if (threadIdx.x == 0) {
        int acc = 0;
        for (int g = 0; g < GG; ++g) { g_offsets[g] = acc; acc += g_counts[g]; }
        g_offsets[GG] = acc;
    }
}

__global__ void pool_partial(const float* __restrict__ h) {
    int g = blockIdx.x;
    int chunk = blockIdx.y;
    int d = threadIdx.x;
    int start = g_offsets[g], end = g_offsets[g + 1];
    int n = end - start;
    int per = (n + (int)gridDim.y - 1) / (int)gridDim.y;
    int s = start + chunk * per;
    int e = min(end, s + per);
    float acc = 0.0f;
    for (int i = s; i < e; ++i) acc += h[(size_t)i * DD + d];
    if (s < e) atomicAdd(&g_pooled[g * DD + d], acc);
}

__global__ void final_linear(const float* __restrict__ lin_w,
                             const float* __restrict__ lin_b,
                             float* __restrict__ out) {
    int t = threadIdx.x;
    int g = t >> 3, c = t & 7;
    float cnt = (float)max(g_counts[g], 1);
    float acc = 0.0f;
    #pragma unroll 16
    for (int d = 0; d < DD; ++d) acc += g_pooled[g * DD + d] * lin_w[d * CC + c];
    out[g * CC + c] = acc / cnt + lin_b[c];
}

// ---------------- launch ----------------
extern "C" void kernel_launch(void* const* d_in, const int* in_sizes, int n_in,
                              void* d_out, int out_size) {
    const float* x     = (const float*)d_in[0];
    const float* W     = (const float*)d_in[1];
    const float* b     = (const float*)d_in[2];
    const float* lin_w = (const float*)d_in[3];
    const float* lin_b = (const float*)d_in[4];
    const int*   ei    = (const int*)d_in[5];
    const int*   batch = (const int*)d_in[6];
    float* out = (float*)d_out;

    __half* xw; float* agg;
    cudaGetSymbolAddress((void**)&xw,  g_xw);
    cudaGetSymbolAddress((void**)&agg, g_agg);

    const int TB = 256;
    int nodeBlocks  = (NN + TB - 1) / TB;
    int edge2Blocks = (2 * EE + TB - 1) / TB;
    int warpBlocks  = (NN * 32 + TB - 1) / TB;
    dim3 gemmGrid((NN + 127) / 128, 2);
    dim3 scanGrid(SCAN_BLOCKS, 2);

    zero_all<<<nodeBlocks, TB>>>();                 // 0
    hist_both<<<edge2Blocks, TB>>>(ei);             // 1
    make_invd<<<nodeBlocks, TB>>>();                // 2
    scan_p1<<<scanGrid, SCAN_TB>>>();               // 3
    scan_p2<<<2, 256>>>();                          // 4
    gemm_tc<false><<<gemmGrid, 256>>>(x, W + 0 * 2 * DD * DD, xw);   // 5 (profiled)
    scan_p3<<<scanGrid, SCAN_TB>>>();               // 6
    csr_fill_both<<<edge2Blocks, TB>>>(ei);         // 7
    gather_both<<<warpBlocks, TB>>>(xw, b + 0 * 2 * DD, agg);        // 8

    gemm_tc<true><<<gemmGrid, 256>>>(agg, W + 1 * 2 * DD * DD, xw);  // 9
    gather_both<<<warpBlocks, TB>>>(xw, b + 1 * 2 * DD, agg);        // 10

    count_batch<<<nodeBlocks, TB>>>(batch);
    scan64<<<1, 32>>>();
    dim3 pg(GG, 8);
    pool_partial<<<pg, DD>>>(agg);
    final_linear<<<1, GG * CC>>>(lin_w, lin_b, out);
}